// round 7
// baseline (speedup 1.0000x reference)
#include <cuda_runtime.h>
#include <cuda_bf16.h>
#include <stdint.h>

#define HH 16
#define SS 4096
#define DD 64

__device__ __align__(16) __nv_bfloat16 g_qhi[HH * SS * DD];
__device__ __align__(16) __nv_bfloat16 g_qlo[HH * SS * DD];
__device__ __align__(16) __nv_bfloat16 g_khi[HH * SS * DD];
__device__ __align__(16) __nv_bfloat16 g_klo[HH * SS * DD];
__device__ __align__(16) __nv_bfloat16 g_vthi[HH * DD * SS];
__device__ __align__(16) __nv_bfloat16 g_vtlo[HH * DD * SS];
__device__ __align__(16) unsigned char g_mask8[(size_t)SS * SS];
__device__ __align__(16) uint32_t g_pp[(size_t)HH * SS * SS];   // packed bf16 hi|lo of exp(s)
__device__ float g_se[(size_t)HH * 64 * SS];
__device__ float g_rowinv[HH * SS];

static __device__ __forceinline__ uint32_t smem_u32(const void* p) {
    uint32_t a;
    asm("{ .reg .u64 t; cvta.to.shared.u64 t, %1; cvt.u32.u64 %0, t; }" : "=r"(a) : "l"(p));
    return a;
}
static __device__ __forceinline__ void ldsm4(uint32_t* r, uint32_t a) {
    asm volatile("ldmatrix.sync.aligned.m8n8.x4.shared.b16 {%0,%1,%2,%3}, [%4];"
        : "=r"(r[0]), "=r"(r[1]), "=r"(r[2]), "=r"(r[3]) : "r"(a));
}
static __device__ __forceinline__ void mma16816(float* c, const uint32_t* a,
                                                uint32_t b0, uint32_t b1) {
    asm volatile("mma.sync.aligned.m16n8k16.row.col.f32.bf16.bf16.f32 "
        "{%0,%1,%2,%3}, {%4,%5,%6,%7}, {%8,%9}, {%0,%1,%2,%3};"
        : "+f"(c[0]), "+f"(c[1]), "+f"(c[2]), "+f"(c[3])
        : "r"(a[0]), "r"(a[1]), "r"(a[2]), "r"(a[3]), "r"(b0), "r"(b1));
}
static __device__ __forceinline__ uint32_t packsplit(float e) {
    __nv_bfloat16 hb = __float2bfloat16(e);
    float hf = __bfloat162float(hb);
    __nv_bfloat16 lb = __float2bfloat16(e - hf);
    return ((uint32_t)__bfloat16_as_ushort(hb) << 16) | (uint32_t)__bfloat16_as_ushort(lb);
}

// ===================== converts =====================
__global__ __launch_bounds__(256) void convert_qk(const float* __restrict__ q,
                                                  const float* __restrict__ k) {
    int i = blockIdx.x * 256 + threadIdx.x;
    float fq = q[i] * 0.125f;
    __nv_bfloat16 qh = __float2bfloat16(fq);
    g_qhi[i] = qh; g_qlo[i] = __float2bfloat16(fq - __bfloat162float(qh));
    float fk = k[i];
    __nv_bfloat16 kh = __float2bfloat16(fk);
    g_khi[i] = kh; g_klo[i] = __float2bfloat16(fk - __bfloat162float(kh));
}
__global__ __launch_bounds__(256) void convert_v(const float* __restrict__ v) {
    __shared__ __nv_bfloat16 th[64][65], tl[64][65];
    const int h = blockIdx.y, s0 = blockIdx.x * 64, tid = threadIdx.x;
#pragma unroll
    for (int j = 0; j < 16; j++) {
        int i = tid + j * 256, sr = i >> 6, d = i & 63;
        float f = v[((size_t)(h * SS + s0 + sr)) * DD + d];
        __nv_bfloat16 hi = __float2bfloat16(f);
        th[sr][d] = hi; tl[sr][d] = __float2bfloat16(f - __bfloat162float(hi));
    }
    __syncthreads();
#pragma unroll
    for (int j = 0; j < 16; j++) {
        int i = tid + j * 256, d = i >> 6, sr = i & 63;
        size_t o = ((size_t)(h * DD + d)) * SS + s0 + sr;
        g_vthi[o] = th[sr][d]; g_vtlo[o] = tl[sr][d];
    }
}
__global__ __launch_bounds__(256) void convert_mask(const int* __restrict__ m) {
    size_t i = ((size_t)blockIdx.x * 256 + threadIdx.x) * 4;
    int4 v = *(const int4*)(m + i);
    uchar4 b;
    b.x = v.x ? 1 : 0; b.y = v.y ? 1 : 0; b.z = v.z ? 1 : 0; b.w = v.w ? 1 : 0;
    *(uchar4*)(g_mask8 + i) = b;
}

// ===================== K1: scores + exp + split + strip sums =====================
// 512 threads, 16 warps: warp_m = wid>>1 (16 q-rows), warp_n = wid&1 (64 k-cols)
#define K1_QHI 0
#define K1_QLO 18432
#define K1_KHI 36864
#define K1_KLO 55296
#define K1_MSK 73728
#define K1_BYTES (K1_MSK + 128 * 144)

__global__ __launch_bounds__(512) void scores_mma() {
    extern __shared__ char sm[];
    const uint32_t sb = smem_u32(sm);
    const int h = blockIdx.x, q0 = blockIdx.y * 128, tid = threadIdx.x;
    const int wid = tid >> 5, lane = tid & 31;

    {   // Q tile (128 x 64), hi+lo
        const __nv_bfloat16* qh = g_qhi + ((size_t)(h * SS + q0)) * DD;
        const __nv_bfloat16* ql = g_qlo + ((size_t)(h * SS + q0)) * DD;
#pragma unroll
        for (int j = 0; j < 2; j++) {
            int i = tid + j * 512, row = i >> 3, u = i & 7;
            *(uint4*)(sm + K1_QHI + row * 144 + u * 16) = *(const uint4*)(qh + row * DD + u * 8);
            *(uint4*)(sm + K1_QLO + row * 144 + u * 16) = *(const uint4*)(ql + row * DD + u * 8);
        }
    }
    const int warp_m = wid >> 1, warp_n = wid & 1;
    const int lr = lane & 15, lc = lane >> 4;
    const uint32_t aoff = sb + K1_QHI + (uint32_t)(warp_m * 16 + lr) * 144 + lc * 16;
    const uint32_t boff = sb + K1_KHI + (uint32_t)(warp_n * 64 + lr) * 144 + lc * 16;

    for (int kt = 0; kt < 32; kt++) {
        {   // K tile + mask bytes
            const __nv_bfloat16* kh = g_khi + ((size_t)(h * SS + kt * 128)) * DD;
            const __nv_bfloat16* kl = g_klo + ((size_t)(h * SS + kt * 128)) * DD;
#pragma unroll
            for (int j = 0; j < 2; j++) {
                int i = tid + j * 512, row = i >> 3, u = i & 7;
                *(uint4*)(sm + K1_KHI + row * 144 + u * 16) = *(const uint4*)(kh + row * DD + u * 8);
                *(uint4*)(sm + K1_KLO + row * 144 + u * 16) = *(const uint4*)(kl + row * DD + u * 8);
                *(uint4*)(sm + K1_MSK + row * 144 + u * 16) =
                    *(const uint4*)(g_mask8 + (size_t)(q0 + row) * SS + kt * 128 + u * 16);
            }
        }
        __syncthreads();

        float acc[8][4];
#pragma unroll
        for (int n = 0; n < 8; n++)
#pragma unroll
            for (int c = 0; c < 4; c++) acc[n][c] = 0.f;

#pragma unroll
        for (int ks = 0; ks < 4; ks++) {
            uint32_t ah[4], al[4];
            ldsm4(ah, aoff + ks * 32);
            ldsm4(al, aoff + 18432 + ks * 32);
#pragma unroll
            for (int ng = 0; ng < 4; ng++) {
                uint32_t bh[4], bl[4];
                ldsm4(bh, boff + ks * 32 + ng * 16 * 144);
                ldsm4(bl, boff + 18432 + ks * 32 + ng * 16 * 144);
                mma16816(acc[2 * ng], ah, bh[0], bh[2]);
                mma16816(acc[2 * ng + 1], ah, bh[1], bh[3]);
                mma16816(acc[2 * ng], ah, bl[0], bl[2]);
                mma16816(acc[2 * ng + 1], ah, bl[1], bl[3]);
                mma16816(acc[2 * ng], al, bh[0], bh[2]);
                mma16816(acc[2 * ng + 1], al, bh[1], bh[3]);
            }
        }
        // epilogue: mask -> exp -> pack/store + strip sums
        const unsigned char* mp = (const unsigned char*)(sm + K1_MSK);
        {
            int rowl = warp_m * 16 + (lane >> 2);
            float sA = 0.f, sB = 0.f;
#pragma unroll
            for (int ng = 0; ng < 8; ng++) {
                int coll = warp_n * 64 + ng * 8 + (lane & 3) * 2;
                uchar2 m0 = *(const uchar2*)(mp + rowl * 144 + coll);
                uchar2 m1 = *(const uchar2*)(mp + (rowl + 8) * 144 + coll);
                float e0 = m0.x ? 0.f : __expf(acc[ng][0]);
                float e1 = m0.y ? 0.f : __expf(acc[ng][1]);
                float e2 = m1.x ? 0.f : __expf(acc[ng][2]);
                float e3 = m1.y ? 0.f : __expf(acc[ng][3]);
                sA += e0 + e1; sB += e2 + e3;
                size_t base = ((size_t)(h * SS + q0 + rowl)) * SS + kt * 128 + coll;
                *(uint2*)(g_pp + base) = make_uint2(packsplit(e0), packsplit(e1));
                *(uint2*)(g_pp + base + 8 * SS) = make_uint2(packsplit(e2), packsplit(e3));
            }
            sA += __shfl_xor_sync(~0u, sA, 1); sA += __shfl_xor_sync(~0u, sA, 2);
            sB += __shfl_xor_sync(~0u, sB, 1); sB += __shfl_xor_sync(~0u, sB, 2);
            if ((lane & 3) == 0) {
                size_t so = ((size_t)(h * 64 + kt * 2 + warp_n)) * SS + q0;
                g_se[so + rowl] = sA; g_se[so + rowl + 8] = sB;
            }
        }
        __syncthreads();
    }
}

// ===================== K2: row inverse sums =====================
__global__ __launch_bounds__(256) void rowinv_kernel() {
    int idx = blockIdx.x * 256 + threadIdx.x;
    int h = idx >> 12, row = idx & 4095;
    float s = 0.f;
#pragma unroll 8
    for (int t = 0; t < 64; t++) s += g_se[((size_t)(h * 64 + t)) * SS + row];
    g_rowinv[idx] = 1.0f / s;
}

// ===================== K3: normalize + attn write + PV =====================
// 512 threads, 16 warps: warp_m = wid>>1 (16 q-rows), warp_n = wid&1 (32 d-cols)
#define K3_PHI 0
#define K3_PLO 34816
#define K3_VHI 69632
#define K3_VLO 87040
#define K3_ROWI 104448
#define K3_BYTES (K3_ROWI + 512)

__global__ __launch_bounds__(512) void pv_mma(float* __restrict__ attn,
                                              float* __restrict__ out) {
    extern __shared__ char sm[];
    const uint32_t sb = smem_u32(sm);
    const int h = blockIdx.x, q0 = blockIdx.y * 128, tid = threadIdx.x;
    const int wid = tid >> 5, lane = tid & 31;
    const int lr = lane & 15, lc = lane >> 4;
    float* rowi = (float*)(sm + K3_ROWI);

    if (tid < 128) rowi[tid] = g_rowinv[h * SS + q0 + tid];
    __syncthreads();

    float acc[4][4];
#pragma unroll
    for (int n = 0; n < 4; n++)
#pragma unroll
        for (int c = 0; c < 4; c++) acc[n][c] = 0.f;

    const int warp_m = wid >> 1, warp_n = wid & 1;
    const uint32_t aoff = sb + K3_PHI + (uint32_t)(warp_m * 16 + lr) * 272 + lc * 16;
    const uint32_t boff = sb + K3_VHI + (uint32_t)(warp_n * 32 + lr) * 272 + lc * 16;

    for (int kt = 0; kt < 32; kt++) {
        const int k0 = kt * 128;
#pragma unroll
        for (int j = 0; j < 8; j++) {  // stage P (unpack) + write final attn
            int i = tid + j * 512, row = i >> 5, c4 = i & 31;
            size_t base = ((size_t)(h * SS + q0 + row)) * SS + k0 + c4 * 4;
            uint4 pp = *(const uint4*)(g_pp + base);
            uint32_t h0, l0, h1, l1;
            asm("prmt.b32 %0, %1, %2, 0x7632;" : "=r"(h0) : "r"(pp.x), "r"(pp.y));
            asm("prmt.b32 %0, %1, %2, 0x5410;" : "=r"(l0) : "r"(pp.x), "r"(pp.y));
            asm("prmt.b32 %0, %1, %2, 0x7632;" : "=r"(h1) : "r"(pp.z), "r"(pp.w));
            asm("prmt.b32 %0, %1, %2, 0x5410;" : "=r"(l1) : "r"(pp.z), "r"(pp.w));
            *(uint2*)(sm + K3_PHI + row * 272 + c4 * 8) = make_uint2(h0, h1);
            *(uint2*)(sm + K3_PLO + row * 272 + c4 * 8) = make_uint2(l0, l1);
            float ri = rowi[row];
            float4 a;
            a.x = (__uint_as_float(pp.x & 0xffff0000u) + __uint_as_float(pp.x << 16)) * ri;
            a.y = (__uint_as_float(pp.y & 0xffff0000u) + __uint_as_float(pp.y << 16)) * ri;
            a.z = (__uint_as_float(pp.z & 0xffff0000u) + __uint_as_float(pp.z << 16)) * ri;
            a.w = (__uint_as_float(pp.w & 0xffff0000u) + __uint_as_float(pp.w << 16)) * ri;
            *(float4*)(attn + base) = a;
        }
#pragma unroll
        for (int j = 0; j < 2; j++) {  // V tiles [64 d][128 k]
            int i = tid + j * 512, d = i >> 4, u = i & 15;
            size_t go = ((size_t)(h * DD + d)) * SS + k0 + u * 8;
            *(uint4*)(sm + K3_VHI + d * 272 + u * 16) = *(const uint4*)(g_vthi + go);
            *(uint4*)(sm + K3_VLO + d * 272 + u * 16) = *(const uint4*)(g_vtlo + go);
        }
        __syncthreads();

#pragma unroll
        for (int ks = 0; ks < 8; ks++) {
            uint32_t ah[4], al[4];
            ldsm4(ah, aoff + ks * 32);
            ldsm4(al, aoff + K3_PLO + ks * 32);
#pragma unroll
            for (int ng = 0; ng < 2; ng++) {
                uint32_t bh[4], bl[4];
                ldsm4(bh, boff + ks * 32 + ng * 16 * 272);
                ldsm4(bl, boff + 17408 + ks * 32 + ng * 16 * 272);
                mma16816(acc[2 * ng], ah, bh[0], bh[2]);
                mma16816(acc[2 * ng + 1], ah, bh[1], bh[3]);
                mma16816(acc[2 * ng], ah, bl[0], bl[2]);
                mma16816(acc[2 * ng + 1], ah, bl[1], bl[3]);
                mma16816(acc[2 * ng], al, bh[0], bh[2]);
                mma16816(acc[2 * ng + 1], al, bh[1], bh[3]);
            }
        }
        __syncthreads();
    }
    const int rowl = warp_m * 16 + (lane >> 2);
    const float riA = rowi[rowl], riB = rowi[rowl + 8];
#pragma unroll
    for (int ng = 0; ng < 4; ng++) {
        int col = warp_n * 32 + ng * 8 + (lane & 3) * 2;
        float* op = out + ((size_t)(h * SS + q0 + rowl)) * DD + col;
        *(float2*)op = make_float2(acc[ng][0] * riA, acc[ng][1] * riA);
        *(float2*)(op + 8 * DD) = make_float2(acc[ng][2] * riB, acc[ng][3] * riB);
    }
}

// ===================== launch =====================
extern "C" void kernel_launch(void* const* d_in, const int* in_sizes, int n_in,
                              void* d_out, int out_size) {
    const float* q = (const float*)d_in[0];
    const float* k = (const float*)d_in[1];
    const float* v = (const float*)d_in[2];
    const int* mask = (const int*)d_in[3];
    float* out = (float*)d_out;
    float* attn = out + (size_t)HH * SS * DD;

    cudaFuncSetAttribute(scores_mma, cudaFuncAttributeMaxDynamicSharedMemorySize, K1_BYTES);
    cudaFuncSetAttribute(pv_mma, cudaFuncAttributeMaxDynamicSharedMemorySize, K3_BYTES);

    convert_qk<<<(HH * SS * DD) / 256, 256>>>(q, k);
    convert_v<<<dim3(SS / 64, HH), 256>>>(v);
    convert_mask<<<(SS * SS) / 1024, 256>>>(mask);
    scores_mma<<<dim3(HH, SS / 128), 512, K1_BYTES>>>();
    rowinv_kernel<<<HH * SS / 256, 256>>>();
    pv_mma<<<dim3(HH, SS / 128), 512, K3_BYTES>>>(attn, out);
}

// round 8
// speedup vs baseline: 1.2040x; 1.2040x over previous
#include <cuda_runtime.h>
#include <cuda_bf16.h>
#include <stdint.h>

#define HH 16
#define SS 4096
#define DD 64

__device__ __align__(16) __nv_bfloat16 g_qhi[HH * SS * DD];
__device__ __align__(16) __nv_bfloat16 g_qlo[HH * SS * DD];
__device__ __align__(16) __nv_bfloat16 g_khi[HH * SS * DD];
__device__ __align__(16) __nv_bfloat16 g_klo[HH * SS * DD];
__device__ __align__(16) __nv_bfloat16 g_vthi[HH * DD * SS];
__device__ __align__(16) __nv_bfloat16 g_vtlo[HH * DD * SS];
__device__ __align__(16) unsigned char g_mask8[(size_t)SS * SS];
__device__ __align__(16) float g_outun[HH * SS * DD];
__device__ float g_se[(size_t)HH * 64 * SS];
__device__ float g_rowinv[HH * SS];

static __device__ __forceinline__ uint32_t smem_u32(const void* p) {
    uint32_t a;
    asm("{ .reg .u64 t; cvta.to.shared.u64 t, %1; cvt.u32.u64 %0, t; }" : "=r"(a) : "l"(p));
    return a;
}
static __device__ __forceinline__ void ldsm4(uint32_t* r, uint32_t a) {
    asm volatile("ldmatrix.sync.aligned.m8n8.x4.shared.b16 {%0,%1,%2,%3}, [%4];"
        : "=r"(r[0]), "=r"(r[1]), "=r"(r[2]), "=r"(r[3]) : "r"(a));
}
static __device__ __forceinline__ void mma16816(float* c, const uint32_t* a,
                                                uint32_t b0, uint32_t b1) {
    asm volatile("mma.sync.aligned.m16n8k16.row.col.f32.bf16.bf16.f32 "
        "{%0,%1,%2,%3}, {%4,%5,%6,%7}, {%8,%9}, {%0,%1,%2,%3};"
        : "+f"(c[0]), "+f"(c[1]), "+f"(c[2]), "+f"(c[3])
        : "r"(a[0]), "r"(a[1]), "r"(a[2]), "r"(a[3]), "r"(b0), "r"(b1));
}
// pack two values' bf16-hi parts (a in low 16, b in high 16); also lo parts
static __device__ __forceinline__ uint32_t packhi2(float a, float b,
                                                   float* ra, float* rb) {
    __nv_bfloat16 ha = __float2bfloat16(a), hb = __float2bfloat16(b);
    *ra = a - __bfloat162float(ha);
    *rb = b - __bfloat162float(hb);
    return ((uint32_t)__bfloat16_as_ushort(hb) << 16) | (uint32_t)__bfloat16_as_ushort(ha);
}
static __device__ __forceinline__ uint32_t packlo2(float ra, float rb) {
    return ((uint32_t)__bfloat16_as_ushort(__float2bfloat16(rb)) << 16) |
           (uint32_t)__bfloat16_as_ushort(__float2bfloat16(ra));
}

// ===================== converts =====================
__global__ __launch_bounds__(256) void convert_qk(const float* __restrict__ q,
                                                  const float* __restrict__ k) {
    int i = blockIdx.x * 256 + threadIdx.x;
    float fq = q[i] * 0.125f;
    __nv_bfloat16 qh = __float2bfloat16(fq);
    g_qhi[i] = qh; g_qlo[i] = __float2bfloat16(fq - __bfloat162float(qh));
    float fk = k[i];
    __nv_bfloat16 kh = __float2bfloat16(fk);
    g_khi[i] = kh; g_klo[i] = __float2bfloat16(fk - __bfloat162float(kh));
}
__global__ __launch_bounds__(256) void convert_v(const float* __restrict__ v) {
    __shared__ __nv_bfloat16 th[64][65], tl[64][65];
    const int h = blockIdx.y, s0 = blockIdx.x * 64, tid = threadIdx.x;
#pragma unroll
    for (int j = 0; j < 16; j++) {
        int i = tid + j * 256, sr = i >> 6, d = i & 63;
        float f = v[((size_t)(h * SS + s0 + sr)) * DD + d];
        __nv_bfloat16 hi = __float2bfloat16(f);
        th[sr][d] = hi; tl[sr][d] = __float2bfloat16(f - __bfloat162float(hi));
    }
    __syncthreads();
#pragma unroll
    for (int j = 0; j < 16; j++) {
        int i = tid + j * 256, d = i >> 6, sr = i & 63;
        size_t o = ((size_t)(h * DD + d)) * SS + s0 + sr;
        g_vthi[o] = th[sr][d]; g_vtlo[o] = tl[sr][d];
    }
}
__global__ __launch_bounds__(256) void convert_mask(const int* __restrict__ m) {
    size_t i = ((size_t)blockIdx.x * 256 + threadIdx.x) * 4;
    int4 v = *(const int4*)(m + i);
    uchar4 b;
    b.x = v.x ? 1 : 0; b.y = v.y ? 1 : 0; b.z = v.z ? 1 : 0; b.w = v.w ? 1 : 0;
    *(uchar4*)(g_mask8 + i) = b;
}

// ===================== K1: fused QK^T + exp + attn-write + PV =====================
// 512 threads, 16 warps.  QK: warp = 16q x 64k.  PV: warp = 16q x 32d.
#define F_QHI 0
#define F_QLO 18432
#define F_KHI 36864
#define F_KLO 55296
#define F_MSK 73728
#define F_PHI 92160
#define F_PLO (F_PHI + 34816)
#define F_VHI (F_PLO + 34816)
#define F_VLO (F_VHI + 17408)
#define F_BYTES (F_VLO + 17408)

__global__ __launch_bounds__(512) void fused_attn(float* __restrict__ attn) {
    extern __shared__ char sm[];
    const uint32_t sb = smem_u32(sm);
    const int h = blockIdx.x, q0 = blockIdx.y * 128, tid = threadIdx.x;
    const int wid = tid >> 5, lane = tid & 31;
    const int warp_m = wid >> 1, warp_n = wid & 1;
    const int lr = lane & 15, lc = lane >> 4;

    {   // persistent Q tile (128 x 64), hi+lo
        const __nv_bfloat16* qh = g_qhi + ((size_t)(h * SS + q0)) * DD;
        const __nv_bfloat16* ql = g_qlo + ((size_t)(h * SS + q0)) * DD;
#pragma unroll
        for (int j = 0; j < 2; j++) {
            int i = tid + j * 512, row = i >> 3, u = i & 7;
            *(uint4*)(sm + F_QHI + row * 144 + u * 16) = *(const uint4*)(qh + row * DD + u * 8);
            *(uint4*)(sm + F_QLO + row * 144 + u * 16) = *(const uint4*)(ql + row * DD + u * 8);
        }
    }
    const uint32_t qk_a = sb + F_QHI + (uint32_t)(warp_m * 16 + lr) * 144 + lc * 16;
    const uint32_t qk_b = sb + F_KHI + (uint32_t)(warp_n * 64 + lr) * 144 + lc * 16;
    const uint32_t pv_a = sb + F_PHI + (uint32_t)(warp_m * 16 + lr) * 272 + lc * 16;
    const uint32_t pv_b = sb + F_VHI + (uint32_t)(warp_n * 32 + lr) * 272 + lc * 16;

    float oacc[4][4];
#pragma unroll
    for (int n = 0; n < 4; n++)
#pragma unroll
        for (int c = 0; c < 4; c++) oacc[n][c] = 0.f;

    for (int kt = 0; kt < 32; kt++) {
        const int k0 = kt * 128;
        __syncthreads();   // PV of kt-1 done before overwriting K/mask/V
        {   // K tile + mask bytes
            const __nv_bfloat16* kh = g_khi + ((size_t)(h * SS + k0)) * DD;
            const __nv_bfloat16* kl = g_klo + ((size_t)(h * SS + k0)) * DD;
#pragma unroll
            for (int j = 0; j < 2; j++) {
                int i = tid + j * 512, row = i >> 3, u = i & 7;
                *(uint4*)(sm + F_KHI + row * 144 + u * 16) = *(const uint4*)(kh + row * DD + u * 8);
                *(uint4*)(sm + F_KLO + row * 144 + u * 16) = *(const uint4*)(kl + row * DD + u * 8);
                *(uint4*)(sm + F_MSK + row * 144 + u * 16) =
                    *(const uint4*)(g_mask8 + (size_t)(q0 + row) * SS + k0 + u * 16);
            }
            // V tiles [64 d][128 k] hi+lo
#pragma unroll
            for (int j = 0; j < 2; j++) {
                int i = tid + j * 512, d = i >> 4, u = i & 15;
                size_t go = ((size_t)(h * DD + d)) * SS + k0 + u * 8;
                *(uint4*)(sm + F_VHI + d * 272 + u * 16) = *(const uint4*)(g_vthi + go);
                *(uint4*)(sm + F_VLO + d * 272 + u * 16) = *(const uint4*)(g_vtlo + go);
            }
        }
        __syncthreads();

        // ---- QK^T MMA (3-product) ----
        float acc[8][4];
#pragma unroll
        for (int n = 0; n < 8; n++)
#pragma unroll
            for (int c = 0; c < 4; c++) acc[n][c] = 0.f;
#pragma unroll
        for (int ks = 0; ks < 4; ks++) {
            uint32_t ah[4], al[4];
            ldsm4(ah, qk_a + ks * 32);
            ldsm4(al, qk_a + 18432 + ks * 32);
#pragma unroll
            for (int ng = 0; ng < 4; ng++) {
                uint32_t bh[4], bl[4];
                ldsm4(bh, qk_b + ks * 32 + ng * 16 * 144);
                ldsm4(bl, qk_b + 18432 + ks * 32 + ng * 16 * 144);
                mma16816(acc[2 * ng], ah, bh[0], bh[2]);
                mma16816(acc[2 * ng + 1], ah, bh[1], bh[3]);
                mma16816(acc[2 * ng], ah, bl[0], bl[2]);
                mma16816(acc[2 * ng + 1], ah, bl[1], bl[3]);
                mma16816(acc[2 * ng], al, bh[0], bh[2]);
                mma16816(acc[2 * ng + 1], al, bh[1], bh[3]);
            }
        }

        // ---- epilogue: mask -> exp -> attn STG + strip sums + P smem ----
        {
            const unsigned char* mp = (const unsigned char*)(sm + F_MSK);
            const int rowl = warp_m * 16 + (lane >> 2);
            float sA = 0.f, sB = 0.f;
#pragma unroll
            for (int ng = 0; ng < 8; ng++) {
                const int coll = warp_n * 64 + ng * 8 + (lane & 3) * 2;
                uchar2 m0 = *(const uchar2*)(mp + rowl * 144 + coll);
                uchar2 m1 = *(const uchar2*)(mp + (rowl + 8) * 144 + coll);
                float e0 = m0.x ? 0.f : __expf(acc[ng][0]);
                float e1 = m0.y ? 0.f : __expf(acc[ng][1]);
                float e2 = m1.x ? 0.f : __expf(acc[ng][2]);
                float e3 = m1.y ? 0.f : __expf(acc[ng][3]);
                sA += e0 + e1; sB += e2 + e3;
                size_t base = ((size_t)(h * SS + q0 + rowl)) * SS + k0 + coll;
                *(float2*)(attn + base) = make_float2(e0, e1);
                *(float2*)(attn + base + 8 * SS) = make_float2(e2, e3);
                float r0, r1, r2, r3;
                uint32_t h01 = packhi2(e0, e1, &r0, &r1);
                uint32_t h23 = packhi2(e2, e3, &r2, &r3);
                *(uint32_t*)(sm + F_PHI + rowl * 272 + coll * 2) = h01;
                *(uint32_t*)(sm + F_PHI + (rowl + 8) * 272 + coll * 2) = h23;
                *(uint32_t*)(sm + F_PLO + rowl * 272 + coll * 2) = packlo2(r0, r1);
                *(uint32_t*)(sm + F_PLO + (rowl + 8) * 272 + coll * 2) = packlo2(r2, r3);
            }
            sA += __shfl_xor_sync(~0u, sA, 1); sA += __shfl_xor_sync(~0u, sA, 2);
            sB += __shfl_xor_sync(~0u, sB, 1); sB += __shfl_xor_sync(~0u, sB, 2);
            if ((lane & 3) == 0) {
                size_t so = ((size_t)(h * 64 + kt * 2 + warp_n)) * SS + q0;
                g_se[so + rowl] = sA; g_se[so + rowl + 8] = sB;
            }
        }
        __syncthreads();

        // ---- PV MMA (3-product), accumulate across kt ----
#pragma unroll
        for (int ks = 0; ks < 8; ks++) {
            uint32_t ah[4], al[4];
            ldsm4(ah, pv_a + ks * 32);
            ldsm4(al, pv_a + 34816 + ks * 32);
#pragma unroll
            for (int ng = 0; ng < 2; ng++) {
                uint32_t bh[4], bl[4];
                ldsm4(bh, pv_b + ks * 32 + ng * 16 * 272);
                ldsm4(bl, pv_b + 17408 + ks * 32 + ng * 16 * 272);
                mma16816(oacc[2 * ng], ah, bh[0], bh[2]);
                mma16816(oacc[2 * ng + 1], ah, bh[1], bh[3]);
                mma16816(oacc[2 * ng], ah, bl[0], bl[2]);
                mma16816(oacc[2 * ng + 1], ah, bl[1], bl[3]);
                mma16816(oacc[2 * ng], al, bh[0], bh[2]);
                mma16816(oacc[2 * ng + 1], al, bh[1], bh[3]);
            }
        }
    }
    // ---- write unnormalized out ----
    const int rowl = warp_m * 16 + (lane >> 2);
#pragma unroll
    for (int ng = 0; ng < 4; ng++) {
        int col = warp_n * 32 + ng * 8 + (lane & 3) * 2;
        float* op = g_outun + ((size_t)(h * SS + q0 + rowl)) * DD + col;
        *(float2*)op = make_float2(oacc[ng][0], oacc[ng][1]);
        *(float2*)(op + 8 * DD) = make_float2(oacc[ng][2], oacc[ng][3]);
    }
}

// ===================== K2: row inverse sums =====================
__global__ __launch_bounds__(256) void rowinv_kernel() {
    int idx = blockIdx.x * 256 + threadIdx.x;
    int h = idx >> 12, row = idx & 4095;
    float s = 0.f;
#pragma unroll 8
    for (int t = 0; t < 64; t++) s += g_se[((size_t)(h * 64 + t)) * SS + row];
    g_rowinv[idx] = 1.0f / s;
}

// ===================== K3n: normalize attn (stream) =====================
__global__ __launch_bounds__(256) void norm_attn(float* __restrict__ attn) {
    const int idx = blockIdx.x;                 // h*4096 + row
    const float ri = g_rowinv[idx];
    float4* p = (float4*)(attn + (size_t)idx * SS);
    const int tid = threadIdx.x;
#pragma unroll
    for (int i = 0; i < 4; i++) {
        float4 v = p[tid + i * 256];
        v.x *= ri; v.y *= ri; v.z *= ri; v.w *= ri;
        p[tid + i * 256] = v;
    }
}

// ===================== K4n: normalize out =====================
__global__ __launch_bounds__(256) void norm_out(float* __restrict__ out) {
    int i = blockIdx.x * 256 + threadIdx.x;
    out[i] = g_outun[i] * g_rowinv[i >> 6];
}

// ===================== launch =====================
extern "C" void kernel_launch(void* const* d_in, const int* in_sizes, int n_in,
                              void* d_out, int out_size) {
    const float* q = (const float*)d_in[0];
    const float* k = (const float*)d_in[1];
    const float* v = (const float*)d_in[2];
    const int* mask = (const int*)d_in[3];
    float* out = (float*)d_out;
    float* attn = out + (size_t)HH * SS * DD;

    cudaFuncSetAttribute(fused_attn, cudaFuncAttributeMaxDynamicSharedMemorySize, F_BYTES);

    convert_qk<<<(HH * SS * DD) / 256, 256>>>(q, k);
    convert_v<<<dim3(SS / 64, HH), 256>>>(v);
    convert_mask<<<(SS * SS) / 1024, 256>>>(mask);
    fused_attn<<<dim3(HH, SS / 128), 512, F_BYTES>>>(attn);
    rowinv_kernel<<<HH * SS / 256, 256>>>();
    norm_attn<<<HH * SS, 256>>>(attn);
    norm_out<<<HH * SS * DD / 256, 256>>>(out);
}

// round 10
// speedup vs baseline: 1.2877x; 1.0696x over previous
#include <cuda_runtime.h>
#include <cuda_bf16.h>
#include <stdint.h>

#define HH 16
#define SS 4096
#define DD 64

__device__ __align__(16) __nv_bfloat16 g_qhi[HH * SS * DD];
__device__ __align__(16) __nv_bfloat16 g_qlo[HH * SS * DD];
__device__ __align__(16) __nv_bfloat16 g_khi[HH * SS * DD];
__device__ __align__(16) __nv_bfloat16 g_klo[HH * SS * DD];
__device__ __align__(16) __nv_bfloat16 g_vthi[HH * DD * SS];
__device__ __align__(16) __nv_bfloat16 g_vtlo[HH * DD * SS];
__device__ __align__(16) unsigned char g_mask8[(size_t)SS * SS];
__device__ __align__(16) float g_outun[HH * SS * DD];
__device__ float g_se[(size_t)HH * 64 * SS];
__device__ float g_rowinv[HH * SS];

static __device__ __forceinline__ uint32_t smem_u32(const void* p) {
    uint32_t a;
    asm("{ .reg .u64 t; cvta.to.shared.u64 t, %1; cvt.u32.u64 %0, t; }" : "=r"(a) : "l"(p));
    return a;
}
static __device__ __forceinline__ void ldsm4(uint32_t* r, uint32_t a) {
    asm volatile("ldmatrix.sync.aligned.m8n8.x4.shared.b16 {%0,%1,%2,%3}, [%4];"
        : "=r"(r[0]), "=r"(r[1]), "=r"(r[2]), "=r"(r[3]) : "r"(a));
}
static __device__ __forceinline__ void mma16816(float* c, const uint32_t* a,
                                                uint32_t b0, uint32_t b1) {
    asm volatile("mma.sync.aligned.m16n8k16.row.col.f32.bf16.bf16.f32 "
        "{%0,%1,%2,%3}, {%4,%5,%6,%7}, {%8,%9}, {%0,%1,%2,%3};"
        : "+f"(c[0]), "+f"(c[1]), "+f"(c[2]), "+f"(c[3])
        : "r"(a[0]), "r"(a[1]), "r"(a[2]), "r"(a[3]), "r"(b0), "r"(b1));
}
static __device__ __forceinline__ void cp16(uint32_t s, const void* g) {
    asm volatile("cp.async.cg.shared.global [%0], [%1], 16;" :: "r"(s), "l"(g));
}
static __device__ __forceinline__ void cp8(uint32_t s, const void* g) {
    asm volatile("cp.async.ca.shared.global [%0], [%1], 8;" :: "r"(s), "l"(g));
}
#define CP_COMMIT() asm volatile("cp.async.commit_group;" ::: "memory")
#define CP_WAIT(n)  asm volatile("cp.async.wait_group %0;" :: "n"(n) : "memory")

static __device__ __forceinline__ uint32_t packhi2(float a, float b,
                                                   float* ra, float* rb) {
    __nv_bfloat16 ha = __float2bfloat16(a), hb = __float2bfloat16(b);
    *ra = a - __bfloat162float(ha);
    *rb = b - __bfloat162float(hb);
    return ((uint32_t)__bfloat16_as_ushort(hb) << 16) | (uint32_t)__bfloat16_as_ushort(ha);
}
static __device__ __forceinline__ uint32_t packlo2(float ra, float rb) {
    return ((uint32_t)__bfloat16_as_ushort(__float2bfloat16(rb)) << 16) |
           (uint32_t)__bfloat16_as_ushort(__float2bfloat16(ra));
}

// ===================== converts =====================
__global__ __launch_bounds__(256) void convert_qk(const float* __restrict__ q,
                                                  const float* __restrict__ k) {
    int i = blockIdx.x * 256 + threadIdx.x;
    float fq = q[i] * 0.125f;
    __nv_bfloat16 qh = __float2bfloat16(fq);
    g_qhi[i] = qh; g_qlo[i] = __float2bfloat16(fq - __bfloat162float(qh));
    float fk = k[i];
    __nv_bfloat16 kh = __float2bfloat16(fk);
    g_khi[i] = kh; g_klo[i] = __float2bfloat16(fk - __bfloat162float(kh));
}
__global__ __launch_bounds__(256) void convert_v(const float* __restrict__ v) {
    __shared__ __nv_bfloat16 th[64][65], tl[64][65];
    const int h = blockIdx.y, s0 = blockIdx.x * 64, tid = threadIdx.x;
#pragma unroll
    for (int j = 0; j < 16; j++) {
        int i = tid + j * 256, sr = i >> 6, d = i & 63;
        float f = v[((size_t)(h * SS + s0 + sr)) * DD + d];
        __nv_bfloat16 hi = __float2bfloat16(f);
        th[sr][d] = hi; tl[sr][d] = __float2bfloat16(f - __bfloat162float(hi));
    }
    __syncthreads();
#pragma unroll
    for (int j = 0; j < 16; j++) {
        int i = tid + j * 256, d = i >> 6, sr = i & 63;
        size_t o = ((size_t)(h * DD + d)) * SS + s0 + sr;
        g_vthi[o] = th[sr][d]; g_vtlo[o] = tl[sr][d];
    }
}
__global__ __launch_bounds__(256) void convert_mask(const int* __restrict__ m) {
    size_t i = ((size_t)blockIdx.x * 256 + threadIdx.x) * 4;
    int4 v = *(const int4*)(m + i);
    uchar4 b;
    b.x = v.x ? 1 : 0; b.y = v.y ? 1 : 0; b.z = v.z ? 1 : 0; b.w = v.w ? 1 : 0;
    *(uchar4*)(g_mask8 + i) = b;
}

// ===================== fused kernel smem layout =====================
#define F_QHI  0          // 128 x 144 (hi), lo at +18432
#define F_K0HI 36864      // K buf0: hi 128x144, lo at +18432
#define F_K1HI 73728      // K buf1
#define F_MSK  110592     // 128 x 136 = 17408
#define F_VHI  128000     // 64 x 272, lo at +17408
#define F_PHI  162816     // 128 x 272, lo at +34816; ends at 232448
#define F_BYTES 232448    // exactly 227 KB = sm_103a per-block max

__global__ __launch_bounds__(512) void fused_attn(float* __restrict__ attn) {
    extern __shared__ char sm[];
    const uint32_t sb = smem_u32(sm);
    const int h = blockIdx.x, q0 = blockIdx.y * 128, tid = threadIdx.x;
    const int wid = tid >> 5, lane = tid & 31;
    const int warp_m = wid >> 1, warp_n = wid & 1;
    const int lr = lane & 15, lc = lane >> 4;

    {   // persistent Q tile (128 x 64), hi+lo
        const __nv_bfloat16* qh = g_qhi + ((size_t)(h * SS + q0)) * DD;
        const __nv_bfloat16* ql = g_qlo + ((size_t)(h * SS + q0)) * DD;
#pragma unroll
        for (int j = 0; j < 2; j++) {
            int i = tid + j * 512, row = i >> 3, u = i & 7;
            *(uint4*)(sm + F_QHI + row * 144 + u * 16) = *(const uint4*)(qh + row * DD + u * 8);
            *(uint4*)(sm + F_QHI + 18432 + row * 144 + u * 16) = *(const uint4*)(ql + row * DD + u * 8);
        }
    }
    {   // prefetch K tile 0 into buf0
        const __nv_bfloat16* kh = g_khi + ((size_t)(h * SS)) * DD;
        const __nv_bfloat16* kl = g_klo + ((size_t)(h * SS)) * DD;
#pragma unroll
        for (int j = 0; j < 2; j++) {
            int i = tid + j * 512, row = i >> 3, u = i & 7;
            cp16(sb + F_K0HI + row * 144 + u * 16, kh + row * DD + u * 8);
            cp16(sb + F_K0HI + 18432 + row * 144 + u * 16, kl + row * DD + u * 8);
        }
        CP_COMMIT();
    }

    const uint32_t qk_a = sb + F_QHI + (uint32_t)(warp_m * 16 + lr) * 144 + lc * 16;
    const uint32_t qk_b0 = sb + F_K0HI + (uint32_t)(warp_n * 64 + lr) * 144 + lc * 16;
    const uint32_t qk_b1 = sb + F_K1HI + (uint32_t)(warp_n * 64 + lr) * 144 + lc * 16;
    const uint32_t pv_a = sb + F_PHI + (uint32_t)(warp_m * 16 + lr) * 272 + lc * 16;
    const uint32_t pv_b = sb + F_VHI + (uint32_t)(warp_n * 32 + lr) * 272 + lc * 16;

    float oacc[4][4];
#pragma unroll
    for (int n = 0; n < 4; n++)
#pragma unroll
        for (int c = 0; c < 4; c++) oacc[n][c] = 0.f;

    for (int kt = 0; kt < 32; kt++) {
        const int k0 = kt * 128;
        CP_WAIT(0);
        __syncthreads();   // K(kt) visible; prev PV done (V/mask bufs free)

        // ---- issue V(kt) + mask(kt) (group 1) ----
#pragma unroll
        for (int j = 0; j < 2; j++) {
            int i = tid + j * 512, d = i >> 4, u = i & 15;
            size_t go = ((size_t)(h * DD + d)) * SS + k0 + u * 8;
            cp16(sb + F_VHI + d * 272 + u * 16, g_vthi + go);
            cp16(sb + F_VHI + 17408 + d * 272 + u * 16, g_vtlo + go);
        }
#pragma unroll
        for (int j = 0; j < 4; j++) {
            int i = tid + j * 512, row = i >> 4, u = i & 15;
            cp8(sb + F_MSK + row * 136 + u * 8,
                g_mask8 + (size_t)(q0 + row) * SS + k0 + u * 8);
        }
        CP_COMMIT();
        // ---- issue K(kt+1) (group 2) ----
        if (kt < 31) {
            const __nv_bfloat16* kh = g_khi + ((size_t)(h * SS + k0 + 128)) * DD;
            const __nv_bfloat16* kl = g_klo + ((size_t)(h * SS + k0 + 128)) * DD;
            const uint32_t kb = (kt & 1) ? F_K0HI : F_K1HI;
#pragma unroll
            for (int j = 0; j < 2; j++) {
                int i = tid + j * 512, row = i >> 3, u = i & 7;
                cp16(sb + kb + row * 144 + u * 16, kh + row * DD + u * 8);
                cp16(sb + kb + 18432 + row * 144 + u * 16, kl + row * DD + u * 8);
            }
            CP_COMMIT();
        }

        // ---- QK^T MMA (3-product) ----
        const uint32_t qk_b = (kt & 1) ? qk_b1 : qk_b0;
        float acc[8][4];
#pragma unroll
        for (int n = 0; n < 8; n++)
#pragma unroll
            for (int c = 0; c < 4; c++) acc[n][c] = 0.f;
#pragma unroll
        for (int ks = 0; ks < 4; ks++) {
            uint32_t ah[4], al[4];
            ldsm4(ah, qk_a + ks * 32);
            ldsm4(al, qk_a + 18432 + ks * 32);
#pragma unroll
            for (int ng = 0; ng < 4; ng++) {
                uint32_t bh[4], bl[4];
                ldsm4(bh, qk_b + ks * 32 + ng * 16 * 144);
                ldsm4(bl, qk_b + 18432 + ks * 32 + ng * 16 * 144);
                mma16816(acc[2 * ng], ah, bh[0], bh[2]);
                mma16816(acc[2 * ng + 1], ah, bh[1], bh[3]);
                mma16816(acc[2 * ng], ah, bl[0], bl[2]);
                mma16816(acc[2 * ng + 1], ah, bl[1], bl[3]);
                mma16816(acc[2 * ng], al, bh[0], bh[2]);
                mma16816(acc[2 * ng + 1], al, bh[1], bh[3]);
            }
        }

        // ---- wait V+mask, keep K(kt+1) in flight ----
        if (kt < 31) { CP_WAIT(1); } else { CP_WAIT(0); }
        __syncthreads();

        // ---- epilogue: mask -> exp -> attn STG + strip sums + P smem ----
        {
            const unsigned char* mp = (const unsigned char*)(sm + F_MSK);
            const int rowl = warp_m * 16 + (lane >> 2);
            float sA = 0.f, sB = 0.f;
#pragma unroll
            for (int ng = 0; ng < 8; ng++) {
                const int coll = warp_n * 64 + ng * 8 + (lane & 3) * 2;
                uchar2 m0 = *(const uchar2*)(mp + rowl * 136 + coll);
                uchar2 m1 = *(const uchar2*)(mp + (rowl + 8) * 136 + coll);
                float e0 = m0.x ? 0.f : __expf(acc[ng][0]);
                float e1 = m0.y ? 0.f : __expf(acc[ng][1]);
                float e2 = m1.x ? 0.f : __expf(acc[ng][2]);
                float e3 = m1.y ? 0.f : __expf(acc[ng][3]);
                sA += e0 + e1; sB += e2 + e3;
                size_t base = ((size_t)(h * SS + q0 + rowl)) * SS + k0 + coll;
                *(float2*)(attn + base) = make_float2(e0, e1);
                *(float2*)(attn + base + 8 * SS) = make_float2(e2, e3);
                float r0, r1, r2, r3;
                uint32_t h01 = packhi2(e0, e1, &r0, &r1);
                uint32_t h23 = packhi2(e2, e3, &r2, &r3);
                *(uint32_t*)(sm + F_PHI + rowl * 272 + coll * 2) = h01;
                *(uint32_t*)(sm + F_PHI + (rowl + 8) * 272 + coll * 2) = h23;
                *(uint32_t*)(sm + F_PHI + 34816 + rowl * 272 + coll * 2) = packlo2(r0, r1);
                *(uint32_t*)(sm + F_PHI + 34816 + (rowl + 8) * 272 + coll * 2) = packlo2(r2, r3);
            }
            sA += __shfl_xor_sync(~0u, sA, 1); sA += __shfl_xor_sync(~0u, sA, 2);
            sB += __shfl_xor_sync(~0u, sB, 1); sB += __shfl_xor_sync(~0u, sB, 2);
            if ((lane & 3) == 0) {
                size_t so = ((size_t)(h * 64 + kt * 2 + warp_n)) * SS + q0;
                g_se[so + rowl] = sA; g_se[so + rowl + 8] = sB;
            }
        }
        __syncthreads();   // P visible

        // ---- PV MMA (3-product), accumulate ----
#pragma unroll
        for (int ks = 0; ks < 8; ks++) {
            uint32_t ah[4], al[4];
            ldsm4(ah, pv_a + ks * 32);
            ldsm4(al, pv_a + 34816 + ks * 32);
#pragma unroll
            for (int ng = 0; ng < 2; ng++) {
                uint32_t bh[4], bl[4];
                ldsm4(bh, pv_b + ks * 32 + ng * 16 * 272);
                ldsm4(bl, pv_b + 17408 + ks * 32 + ng * 16 * 272);
                mma16816(oacc[2 * ng], ah, bh[0], bh[2]);
                mma16816(oacc[2 * ng + 1], ah, bh[1], bh[3]);
                mma16816(oacc[2 * ng], ah, bl[0], bl[2]);
                mma16816(oacc[2 * ng + 1], ah, bl[1], bl[3]);
                mma16816(oacc[2 * ng], al, bh[0], bh[2]);
                mma16816(oacc[2 * ng + 1], al, bh[1], bh[3]);
            }
        }
    }
    // ---- write unnormalized out ----
    const int rowl = warp_m * 16 + (lane >> 2);
#pragma unroll
    for (int ng = 0; ng < 4; ng++) {
        int col = warp_n * 32 + ng * 8 + (lane & 3) * 2;
        float* op = g_outun + ((size_t)(h * SS + q0 + rowl)) * DD + col;
        *(float2*)op = make_float2(oacc[ng][0], oacc[ng][1]);
        *(float2*)(op + 8 * DD) = make_float2(oacc[ng][2], oacc[ng][3]);
    }
}

// ===================== row inverse sums =====================
__global__ __launch_bounds__(256) void rowinv_kernel() {
    int idx = blockIdx.x * 256 + threadIdx.x;
    int h = idx >> 12, row = idx & 4095;
    float s = 0.f;
#pragma unroll 8
    for (int t = 0; t < 64; t++) s += g_se[((size_t)(h * 64 + t)) * SS + row];
    g_rowinv[idx] = 1.0f / s;
}

// ===================== normalize attn (stream) =====================
__global__ __launch_bounds__(256) void norm_attn(float* __restrict__ attn) {
    const int idx = blockIdx.x;
    const float ri = g_rowinv[idx];
    float4* p = (float4*)(attn + (size_t)idx * SS);
    const int tid = threadIdx.x;
#pragma unroll
    for (int i = 0; i < 4; i++) {
        float4 v = p[tid + i * 256];
        v.x *= ri; v.y *= ri; v.z *= ri; v.w *= ri;
        p[tid + i * 256] = v;
    }
}

// ===================== normalize out =====================
__global__ __launch_bounds__(256) void norm_out(float* __restrict__ out) {
    int i = blockIdx.x * 256 + threadIdx.x;
    out[i] = g_outun[i] * g_rowinv[i >> 6];
}

// ===================== launch =====================
extern "C" void kernel_launch(void* const* d_in, const int* in_sizes, int n_in,
                              void* d_out, int out_size) {
    const float* q = (const float*)d_in[0];
    const float* k = (const float*)d_in[1];
    const float* v = (const float*)d_in[2];
    const int* mask = (const int*)d_in[3];
    float* out = (float*)d_out;
    float* attn = out + (size_t)HH * SS * DD;

    cudaFuncSetAttribute(fused_attn, cudaFuncAttributeMaxDynamicSharedMemorySize, F_BYTES);

    convert_qk<<<(HH * SS * DD) / 256, 256>>>(q, k);
    convert_v<<<dim3(SS / 64, HH), 256>>>(v);
    convert_mask<<<(SS * SS) / 1024, 256>>>(mask);
    fused_attn<<<dim3(HH, SS / 128), 512, F_BYTES>>>(attn);
    rowinv_kernel<<<HH * SS / 256, 256>>>();
    norm_attn<<<HH * SS, 256>>>(attn);
    norm_out<<<HH * SS * DD / 256, 256>>>(out);
}

// round 11
// speedup vs baseline: 1.3466x; 1.0457x over previous
#include <cuda_runtime.h>
#include <cuda_bf16.h>
#include <stdint.h>

#define HH 16
#define SS 4096
#define DD 64

__device__ __align__(16) __nv_bfloat16 g_qhi[HH * SS * DD];
__device__ __align__(16) __nv_bfloat16 g_qlo[HH * SS * DD];
__device__ __align__(16) __nv_bfloat16 g_khi[HH * SS * DD];
__device__ __align__(16) __nv_bfloat16 g_klo[HH * SS * DD];
__device__ __align__(16) __nv_bfloat16 g_vthi[HH * DD * SS];
__device__ __align__(16) __nv_bfloat16 g_vtlo[HH * DD * SS];
__device__ __align__(16) unsigned char g_mask8[(size_t)SS * SS];
__device__ __align__(16) float g_outun[HH * SS * DD];
__device__ float g_se[(size_t)HH * 32 * SS];
__device__ float g_rowinv[HH * SS];

static __device__ __forceinline__ uint32_t smem_u32(const void* p) {
    uint32_t a;
    asm("{ .reg .u64 t; cvta.to.shared.u64 t, %1; cvt.u32.u64 %0, t; }" : "=r"(a) : "l"(p));
    return a;
}
static __device__ __forceinline__ void ldsm4(uint32_t* r, uint32_t a) {
    asm volatile("ldmatrix.sync.aligned.m8n8.x4.shared.b16 {%0,%1,%2,%3}, [%4];"
        : "=r"(r[0]), "=r"(r[1]), "=r"(r[2]), "=r"(r[3]) : "r"(a));
}
static __device__ __forceinline__ void mma16816(float* c, const uint32_t* a,
                                                uint32_t b0, uint32_t b1) {
    asm volatile("mma.sync.aligned.m16n8k16.row.col.f32.bf16.bf16.f32 "
        "{%0,%1,%2,%3}, {%4,%5,%6,%7}, {%8,%9}, {%0,%1,%2,%3};"
        : "+f"(c[0]), "+f"(c[1]), "+f"(c[2]), "+f"(c[3])
        : "r"(a[0]), "r"(a[1]), "r"(a[2]), "r"(a[3]), "r"(b0), "r"(b1));
}
static __device__ __forceinline__ void cp16(uint32_t s, const void* g) {
    asm volatile("cp.async.cg.shared.global [%0], [%1], 16;" :: "r"(s), "l"(g));
}
#define CP_COMMIT() asm volatile("cp.async.commit_group;" ::: "memory")
#define CP_WAIT(n)  asm volatile("cp.async.wait_group %0;" :: "n"(n) : "memory")

static __device__ __forceinline__ uint32_t packhi2(float a, float b,
                                                   float* ra, float* rb) {
    __nv_bfloat16 ha = __float2bfloat16(a), hb = __float2bfloat16(b);
    *ra = a - __bfloat162float(ha);
    *rb = b - __bfloat162float(hb);
    return ((uint32_t)__bfloat16_as_ushort(hb) << 16) | (uint32_t)__bfloat16_as_ushort(ha);
}
static __device__ __forceinline__ uint32_t packlo2(float ra, float rb) {
    return ((uint32_t)__bfloat16_as_ushort(__float2bfloat16(rb)) << 16) |
           (uint32_t)__bfloat16_as_ushort(__float2bfloat16(ra));
}

// ===================== converts =====================
__global__ __launch_bounds__(256) void convert_qk(const float* __restrict__ q,
                                                  const float* __restrict__ k) {
    int i = blockIdx.x * 256 + threadIdx.x;
    float fq = q[i] * 0.125f;
    __nv_bfloat16 qh = __float2bfloat16(fq);
    g_qhi[i] = qh; g_qlo[i] = __float2bfloat16(fq - __bfloat162float(qh));
    float fk = k[i];
    __nv_bfloat16 kh = __float2bfloat16(fk);
    g_khi[i] = kh; g_klo[i] = __float2bfloat16(fk - __bfloat162float(kh));
}
__global__ __launch_bounds__(256) void convert_v(const float* __restrict__ v) {
    __shared__ __nv_bfloat16 th[64][65], tl[64][65];
    const int h = blockIdx.y, s0 = blockIdx.x * 64, tid = threadIdx.x;
#pragma unroll
    for (int j = 0; j < 16; j++) {
        int i = tid + j * 256, sr = i >> 6, d = i & 63;
        float f = v[((size_t)(h * SS + s0 + sr)) * DD + d];
        __nv_bfloat16 hi = __float2bfloat16(f);
        th[sr][d] = hi; tl[sr][d] = __float2bfloat16(f - __bfloat162float(hi));
    }
    __syncthreads();
#pragma unroll
    for (int j = 0; j < 16; j++) {
        int i = tid + j * 256, d = i >> 6, sr = i & 63;
        size_t o = ((size_t)(h * DD + d)) * SS + s0 + sr;
        g_vthi[o] = th[sr][d]; g_vtlo[o] = tl[sr][d];
    }
}
__global__ __launch_bounds__(256) void convert_mask(const int* __restrict__ m) {
    size_t i = ((size_t)blockIdx.x * 256 + threadIdx.x) * 4;
    int4 v = *(const int4*)(m + i);
    uchar4 b;
    b.x = v.x ? 1 : 0; b.y = v.y ? 1 : 0; b.z = v.z ? 1 : 0; b.w = v.w ? 1 : 0;
    *(uchar4*)(g_mask8 + i) = b;
}

// ===================== fused kernel smem =====================
#define F_QHI 0          // 128x144 hi, lo at +18432 (36864)
#define F_K0  36864      // buf: hi 128x144, lo +18432 (36864 each)
#define F_K1  73728
#define F_V0  110592     // buf: hi 64x272, lo +17408 (34816 each)
#define F_V1  145408
#define F_M0  180224     // 128x144 (18432 each)
#define F_M1  198656
#define F_BYTES 217088

__global__ __launch_bounds__(256) void fused_attn(float* __restrict__ attn) {
    extern __shared__ char sm[];
    const uint32_t sb = smem_u32(sm);
    const int h = blockIdx.x, q0 = blockIdx.y * 128, tid = threadIdx.x;
    const int wid = tid >> 5, lane = tid & 31;
    const int lr = lane & 15, lc = lane >> 4;
    const int lam = lane & 3, r4 = lane >> 2;

    // prefetch tile 0 (K, V, mask) into buf 0
    {
        const __nv_bfloat16* kh = g_khi + ((size_t)(h * SS)) * DD;
        const __nv_bfloat16* kl = g_klo + ((size_t)(h * SS)) * DD;
#pragma unroll
        for (int j = 0; j < 4; j++) {
            int i = tid + j * 256, row = i >> 3, u = i & 7;
            cp16(sb + F_K0 + row * 144 + u * 16, kh + row * DD + u * 8);
            cp16(sb + F_K0 + 18432 + row * 144 + u * 16, kl + row * DD + u * 8);
        }
#pragma unroll
        for (int j = 0; j < 4; j++) {
            int i = tid + j * 256, d = i >> 4, u = i & 15;
            size_t go = ((size_t)(h * DD + d)) * SS + u * 8;
            cp16(sb + F_V0 + d * 272 + u * 16, g_vthi + go);
            cp16(sb + F_V0 + 17408 + d * 272 + u * 16, g_vtlo + go);
        }
#pragma unroll
        for (int j = 0; j < 4; j++) {
            int i = tid + j * 256, row = i >> 3, u = i & 7;
            cp16(sb + F_M0 + row * 144 + u * 16,
                 g_mask8 + (size_t)(q0 + row) * SS + u * 16);
        }
        CP_COMMIT();
    }
    // persistent Q tile (plain stores, consumed after first sync)
    {
        const __nv_bfloat16* qh = g_qhi + ((size_t)(h * SS + q0)) * DD;
        const __nv_bfloat16* ql = g_qlo + ((size_t)(h * SS + q0)) * DD;
#pragma unroll
        for (int j = 0; j < 4; j++) {
            int i = tid + j * 256, row = i >> 3, u = i & 7;
            *(uint4*)(sm + F_QHI + row * 144 + u * 16) = *(const uint4*)(qh + row * DD + u * 8);
            *(uint4*)(sm + F_QHI + 18432 + row * 144 + u * 16) = *(const uint4*)(ql + row * DD + u * 8);
        }
    }

    const uint32_t qa = sb + F_QHI + (uint32_t)(wid * 16 + lr) * 144 + lc * 16;
    float oacc[8][4];
#pragma unroll
    for (int n = 0; n < 8; n++)
#pragma unroll
        for (int c = 0; c < 4; c++) oacc[n][c] = 0.f;

    for (int kt = 0; kt < 32; kt++) {
        CP_WAIT(0);
        __syncthreads();
        // prefetch kt+1 into other buf
        if (kt < 31) {
            const int kn = (kt + 1) * 128;
            const int nb = (kt + 1) & 1;
            const uint32_t kb = sb + (nb ? F_K1 : F_K0);
            const uint32_t vb = sb + (nb ? F_V1 : F_V0);
            const uint32_t mb = sb + (nb ? F_M1 : F_M0);
            const __nv_bfloat16* kh = g_khi + ((size_t)(h * SS + kn)) * DD;
            const __nv_bfloat16* kl = g_klo + ((size_t)(h * SS + kn)) * DD;
#pragma unroll
            for (int j = 0; j < 4; j++) {
                int i = tid + j * 256, row = i >> 3, u = i & 7;
                cp16(kb + row * 144 + u * 16, kh + row * DD + u * 8);
                cp16(kb + 18432 + row * 144 + u * 16, kl + row * DD + u * 8);
            }
#pragma unroll
            for (int j = 0; j < 4; j++) {
                int i = tid + j * 256, d = i >> 4, u = i & 15;
                size_t go = ((size_t)(h * DD + d)) * SS + kn + u * 8;
                cp16(vb + d * 272 + u * 16, g_vthi + go);
                cp16(vb + 17408 + d * 272 + u * 16, g_vtlo + go);
            }
#pragma unroll
            for (int j = 0; j < 4; j++) {
                int i = tid + j * 256, row = i >> 3, u = i & 7;
                cp16(mb + row * 144 + u * 16,
                     g_mask8 + (size_t)(q0 + row) * SS + kn + u * 16);
            }
            CP_COMMIT();
        }
        const uint32_t kbase = sb + ((kt & 1) ? F_K1 : F_K0);
        const uint32_t vbase = sb + ((kt & 1) ? F_V1 : F_V0);
        const char* mbase = sm + ((kt & 1) ? F_M1 : F_M0);
        const int k0 = kt * 128;

        // ---- QK^T: warp tile 16q x 128k (3-product) ----
        float acc[16][4];
#pragma unroll
        for (int n = 0; n < 16; n++)
#pragma unroll
            for (int c = 0; c < 4; c++) acc[n][c] = 0.f;
#pragma unroll
        for (int ks = 0; ks < 4; ks++) {
            uint32_t ah[4], al[4];
            ldsm4(ah, qa + ks * 32);
            ldsm4(al, qa + 18432 + ks * 32);
#pragma unroll
            for (int cg = 0; cg < 8; cg++) {
                uint32_t bh[4], bl[4];
                const uint32_t kadr = kbase + (uint32_t)(cg * 16 + lr) * 144 + lc * 16 + ks * 32;
                ldsm4(bh, kadr);
                ldsm4(bl, kadr + 18432);
                mma16816(acc[2 * cg], ah, bh[0], bh[2]);
                mma16816(acc[2 * cg + 1], ah, bh[1], bh[3]);
                mma16816(acc[2 * cg], ah, bl[0], bl[2]);
                mma16816(acc[2 * cg + 1], ah, bl[1], bl[3]);
                mma16816(acc[2 * cg], al, bh[0], bh[2]);
                mma16816(acc[2 * cg + 1], al, bh[1], bh[3]);
            }
        }

        // ---- per 16-col group: exp -> attn STG -> register A-frags -> PV ----
        const int rowl = wid * 16 + r4;
        float sA = 0.f, sB = 0.f;
#pragma unroll
        for (int cg = 0; cg < 8; cg++) {
            const int cb = cg * 16 + lam * 2;
            uchar2 mA0 = *(const uchar2*)(mbase + rowl * 144 + cb);
            uchar2 mA8 = *(const uchar2*)(mbase + rowl * 144 + cb + 8);
            uchar2 mB0 = *(const uchar2*)(mbase + (rowl + 8) * 144 + cb);
            uchar2 mB8 = *(const uchar2*)(mbase + (rowl + 8) * 144 + cb + 8);
            float eA0 = mA0.x ? 0.f : __expf(acc[2 * cg][0]);
            float eA1 = mA0.y ? 0.f : __expf(acc[2 * cg][1]);
            float eB0 = mB0.x ? 0.f : __expf(acc[2 * cg][2]);
            float eB1 = mB0.y ? 0.f : __expf(acc[2 * cg][3]);
            float eA8 = mA8.x ? 0.f : __expf(acc[2 * cg + 1][0]);
            float eA9 = mA8.y ? 0.f : __expf(acc[2 * cg + 1][1]);
            float eB8 = mB8.x ? 0.f : __expf(acc[2 * cg + 1][2]);
            float eB9 = mB8.y ? 0.f : __expf(acc[2 * cg + 1][3]);
            sA += (eA0 + eA1) + (eA8 + eA9);
            sB += (eB0 + eB1) + (eB8 + eB9);
            size_t base = ((size_t)(h * SS + q0 + rowl)) * SS + k0 + cb;
            *(float2*)(attn + base) = make_float2(eA0, eA1);
            *(float2*)(attn + base + 8) = make_float2(eA8, eA9);
            *(float2*)(attn + base + 8 * SS) = make_float2(eB0, eB1);
            *(float2*)(attn + base + 8 * SS + 8) = make_float2(eB8, eB9);
            // C-frag -> A-frag (register reuse, no smem)
            float rA0, rA1, rB0, rB1, rA8, rA9, rB8, rB9;
            uint32_t pah[4], pal[4];
            pah[0] = packhi2(eA0, eA1, &rA0, &rA1);
            pah[1] = packhi2(eB0, eB1, &rB0, &rB1);
            pah[2] = packhi2(eA8, eA9, &rA8, &rA9);
            pah[3] = packhi2(eB8, eB9, &rB8, &rB9);
            pal[0] = packlo2(rA0, rA1);
            pal[1] = packlo2(rB0, rB1);
            pal[2] = packlo2(rA8, rA9);
            pal[3] = packlo2(rB8, rB9);
#pragma unroll
            for (int ng = 0; ng < 4; ng++) {
                uint32_t vh[4], vl[4];
                const uint32_t vadr = vbase + (uint32_t)(ng * 16 + lr) * 272 + lc * 16 + cg * 32;
                ldsm4(vh, vadr);
                ldsm4(vl, vadr + 17408);
                mma16816(oacc[2 * ng], pah, vh[0], vh[2]);
                mma16816(oacc[2 * ng + 1], pah, vh[1], vh[3]);
                mma16816(oacc[2 * ng], pah, vl[0], vl[2]);
                mma16816(oacc[2 * ng + 1], pah, vl[1], vl[3]);
                mma16816(oacc[2 * ng], pal, vh[0], vh[2]);
                mma16816(oacc[2 * ng + 1], pal, vh[1], vh[3]);
            }
        }
        sA += __shfl_xor_sync(~0u, sA, 1); sA += __shfl_xor_sync(~0u, sA, 2);
        sB += __shfl_xor_sync(~0u, sB, 1); sB += __shfl_xor_sync(~0u, sB, 2);
        if (lam == 0) {
            size_t so = ((size_t)(h * 32 + kt)) * SS + q0;
            g_se[so + rowl] = sA;
            g_se[so + rowl + 8] = sB;
        }
    }
    // ---- write unnormalized out ----
    const int rowl = wid * 16 + r4;
#pragma unroll
    for (int nb = 0; nb < 8; nb++) {
        int col = nb * 8 + lam * 2;
        float* op = g_outun + ((size_t)(h * SS + q0 + rowl)) * DD + col;
        *(float2*)op = make_float2(oacc[nb][0], oacc[nb][1]);
        *(float2*)(op + 8 * DD) = make_float2(oacc[nb][2], oacc[nb][3]);
    }
}

// ===================== row inverse sums =====================
__global__ __launch_bounds__(256) void rowinv_kernel() {
    int idx = blockIdx.x * 256 + threadIdx.x;
    int h = idx >> 12, row = idx & 4095;
    float s = 0.f;
#pragma unroll 8
    for (int t = 0; t < 32; t++) s += g_se[((size_t)(h * 32 + t)) * SS + row];
    g_rowinv[idx] = 1.0f / s;
}

// ===================== normalize attn (stream) =====================
__global__ __launch_bounds__(256) void norm_attn(float* __restrict__ attn) {
    const int idx = blockIdx.x;
    const float ri = g_rowinv[idx];
    float4* p = (float4*)(attn + (size_t)idx * SS);
    const int tid = threadIdx.x;
#pragma unroll
    for (int i = 0; i < 4; i++) {
        float4 v = p[tid + i * 256];
        v.x *= ri; v.y *= ri; v.z *= ri; v.w *= ri;
        p[tid + i * 256] = v;
    }
}

// ===================== normalize out =====================
__global__ __launch_bounds__(256) void norm_out(float* __restrict__ out) {
    int i = blockIdx.x * 256 + threadIdx.x;
    out[i] = g_outun[i] * g_rowinv[i >> 6];
}

// ===================== launch =====================
extern "C" void kernel_launch(void* const* d_in, const int* in_sizes, int n_in,
                              void* d_out, int out_size) {
    const float* q = (const float*)d_in[0];
    const float* k = (const float*)d_in[1];
    const float* v = (const float*)d_in[2];
    const int* mask = (const int*)d_in[3];
    float* out = (float*)d_out;
    float* attn = out + (size_t)HH * SS * DD;

    cudaFuncSetAttribute(fused_attn, cudaFuncAttributeMaxDynamicSharedMemorySize, F_BYTES);

    convert_qk<<<(HH * SS * DD) / 256, 256>>>(q, k);
    convert_v<<<dim3(SS / 64, HH), 256>>>(v);
    convert_mask<<<(SS * SS) / 1024, 256>>>(mask);
    fused_attn<<<dim3(HH, SS / 128), 256, F_BYTES>>>(attn);
    rowinv_kernel<<<HH * SS / 256, 256>>>();
    norm_attn<<<HH * SS, 256>>>(attn);
    norm_out<<<HH * SS * DD / 256, 256>>>(out);
}